// round 6
// baseline (speedup 1.0000x reference)
#include <cuda_runtime.h>

#define N_JOINTS      55
#define BLOCK_THREADS 128
#define VERTS_PER_BLOCK 256   // 2 vertices per thread

typedef unsigned long long ull;

// Packed f32x2 FMA (Blackwell sm_100+): d = a*b + c on two packed fp32 lanes.
__device__ __forceinline__ ull fma2(ull a, ull b, ull c) {
    ull d;
    asm("fma.rn.f32x2 %0, %1, %2, %3;" : "=l"(d) : "l"(a), "l"(b), "l"(c));
    return d;
}
__device__ __forceinline__ ull pack2(float x, float y) {
    ull d;
    unsigned xi = __float_as_uint(x), yi = __float_as_uint(y);
    asm("mov.b64 %0, {%1, %2};" : "=l"(d) : "r"(xi), "r"(yi));
    return d;
}
__device__ __forceinline__ ull dup2(float x) {
    ull d;
    unsigned xi = __float_as_uint(x);
    asm("mov.b64 %0, {%1, %1};" : "=l"(d) : "r"(xi));
    return d;
}
__device__ __forceinline__ float2 unpack2(ull v) {
    unsigned lo, hi;
    asm("mov.b64 {%0, %1}, %2;" : "=r"(lo), "=r"(hi) : "l"(v));
    float2 r;
    r.x = __uint_as_float(lo);
    r.y = __uint_as_float(hi);
    return r;
}

extern __shared__ unsigned char smem_raw[];

__global__ __launch_bounds__(BLOCK_THREADS)
void lbs_kernel(const float* __restrict__ points,
                const float* __restrict__ weights,
                const float* __restrict__ SE3,
                float* __restrict__ out,
                int n_verts)
{
    // SMEM layout: [165 x ulonglong2] packed SE3 top-3 rows, then [256*55] weight tile.
    ulonglong2* se3s = (ulonglong2*)smem_raw;
    float* wsm = (float*)(smem_raw + (size_t)N_JOINTS * 3 * sizeof(ulonglong2));

    const int t = threadIdx.x;
    const long long base = (long long)blockIdx.x * VERTS_PER_BLOCK;

    // ---- Stage SE3: pack top 3 rows of each joint as f32x2 pairs ----
    // SE3 global: [55][4][4] fp32, row-major -> joint j, row r is a 16B-aligned float4.
    const float4* se3g = (const float4*)SE3;
    for (int i = t; i < N_JOINTS * 3; i += BLOCK_THREADS) {
        int j = i / 3;
        int r = i - 3 * j;
        float4 v = se3g[j * 4 + r];
        ulonglong2 q;
        q.x = pack2(v.x, v.y);   // (m_r0, m_r1)
        q.y = pack2(v.z, v.w);   // (m_r2, m_r3)
        se3s[i] = q;
    }

    // ---- Stage weight tile: coalesced float4 flat copy ----
    long long rows_ll = (long long)n_verts - base;
    int rows = rows_ll > VERTS_PER_BLOCK ? VERTS_PER_BLOCK : (int)rows_ll;
    int total = rows * N_JOINTS;
    const float* wg = weights + base * N_JOINTS;       // base*55*4 bytes: 16B-aligned (base mult of 256)
    const float4* wg4 = (const float4*)wg;
    float4* ws4 = (float4*)wsm;
    int nf4 = total >> 2;
    for (int i = t; i < nf4; i += BLOCK_THREADS) {
        ws4[i] = wg4[i];
    }
    for (int i = (nf4 << 2) + t; i < total; i += BLOCK_THREADS) {
        wsm[i] = wg[i];
    }
    __syncthreads();

    // ---- Compute: 2 vertices per thread ----
    const long long n0 = base + t;
    const long long n1 = base + t + BLOCK_THREADS;
    const bool ok0 = n0 < n_verts;
    const bool ok1 = n1 < n_verts;

    ull a0 = 0, a1 = 0, a2 = 0, a3 = 0, a4 = 0, a5 = 0;   // vertex 0: (A00,A01)(A02,A03)(A10,A11)(A12,A13)(A20,A21)(A22,A23)
    ull b0 = 0, b1 = 0, b2 = 0, b3 = 0, b4 = 0, b5 = 0;   // vertex 1

    const float* w0p = wsm + t * N_JOINTS;                   // lane stride 55 floats: gcd(55,32)=1 -> conflict-free
    const float* w1p = wsm + (t + BLOCK_THREADS) * N_JOINTS;

    #pragma unroll 11
    for (int j = 0; j < N_JOINTS; j++) {
        ulonglong2 q0 = se3s[3 * j + 0];   // broadcast LDS.128
        ulonglong2 q1 = se3s[3 * j + 1];
        ulonglong2 q2 = se3s[3 * j + 2];
        ull wa = dup2(w0p[j]);
        ull wb = dup2(w1p[j]);
        a0 = fma2(wa, q0.x, a0);  a1 = fma2(wa, q0.y, a1);
        a2 = fma2(wa, q1.x, a2);  a3 = fma2(wa, q1.y, a3);
        a4 = fma2(wa, q2.x, a4);  a5 = fma2(wa, q2.y, a5);
        b0 = fma2(wb, q0.x, b0);  b1 = fma2(wb, q0.y, b1);
        b2 = fma2(wb, q1.x, b2);  b3 = fma2(wb, q1.y, b3);
        b4 = fma2(wb, q2.x, b4);  b5 = fma2(wb, q2.y, b5);
    }

    // ---- Epilogue: out = R*p + T per vertex ----
    if (ok0) {
        const float* pp = points + n0 * 3;
        float px = pp[0], py = pp[1], pz = pp[2];
        float2 r0 = unpack2(a0), r1 = unpack2(a1);
        float2 r2 = unpack2(a2), r3 = unpack2(a3);
        float2 r4 = unpack2(a4), r5 = unpack2(a5);
        float* op = out + n0 * 3;
        op[0] = fmaf(r0.x, px, fmaf(r0.y, py, fmaf(r1.x, pz, r1.y)));
        op[1] = fmaf(r2.x, px, fmaf(r2.y, py, fmaf(r3.x, pz, r3.y)));
        op[2] = fmaf(r4.x, px, fmaf(r4.y, py, fmaf(r5.x, pz, r5.y)));
    }
    if (ok1) {
        const float* pp = points + n1 * 3;
        float px = pp[0], py = pp[1], pz = pp[2];
        float2 r0 = unpack2(b0), r1 = unpack2(b1);
        float2 r2 = unpack2(b2), r3 = unpack2(b3);
        float2 r4 = unpack2(b4), r5 = unpack2(b5);
        float* op = out + n1 * 3;
        op[0] = fmaf(r0.x, px, fmaf(r0.y, py, fmaf(r1.x, pz, r1.y)));
        op[1] = fmaf(r2.x, px, fmaf(r2.y, py, fmaf(r3.x, pz, r3.y)));
        op[2] = fmaf(r4.x, px, fmaf(r4.y, py, fmaf(r5.x, pz, r5.y)));
    }
}

extern "C" void kernel_launch(void* const* d_in, const int* in_sizes, int n_in,
                              void* d_out, int out_size)
{
    const float* points  = (const float*)d_in[0];  // [N, 3]
    const float* weights = (const float*)d_in[1];  // [N, 55]
    const float* SE3     = (const float*)d_in[2];  // [55, 4, 4]
    float* out = (float*)d_out;                    // [N, 3]

    const int n_verts = in_sizes[0] / 3;
    const int nblocks = (n_verts + VERTS_PER_BLOCK - 1) / VERTS_PER_BLOCK;
    const size_t smem = (size_t)N_JOINTS * 3 * sizeof(ulonglong2)
                      + (size_t)VERTS_PER_BLOCK * N_JOINTS * sizeof(float);  // 58,960 B

    cudaFuncSetAttribute(lbs_kernel, cudaFuncAttributeMaxDynamicSharedMemorySize, (int)smem);
    lbs_kernel<<<nblocks, BLOCK_THREADS, smem>>>(points, weights, SE3, out, n_verts);
}

// round 9
// speedup vs baseline: 1.0080x; 1.0080x over previous
#include <cuda_runtime.h>

#define N_JOINTS        55
#define BLOCK_THREADS   128
#define VERTS_PER_BLOCK 128   // 1 vertex per thread -> smem 30,800 B -> 7 CTAs/SM

typedef unsigned long long ull;

// Packed f32x2 FMA (Blackwell sm_100+): d = a*b + c on two packed fp32 lanes.
__device__ __forceinline__ ull fma2(ull a, ull b, ull c) {
    ull d;
    asm("fma.rn.f32x2 %0, %1, %2, %3;" : "=l"(d) : "l"(a), "l"(b), "l"(c));
    return d;
}
__device__ __forceinline__ ull pack2(float x, float y) {
    ull d;
    unsigned xi = __float_as_uint(x), yi = __float_as_uint(y);
    asm("mov.b64 %0, {%1, %2};" : "=l"(d) : "r"(xi), "r"(yi));
    return d;
}
__device__ __forceinline__ ull dup2(float x) {
    ull d;
    unsigned xi = __float_as_uint(x);
    asm("mov.b64 %0, {%1, %1};" : "=l"(d) : "r"(xi));
    return d;
}
__device__ __forceinline__ float2 unpack2(ull v) {
    unsigned lo, hi;
    asm("mov.b64 {%0, %1}, %2;" : "=r"(lo), "=r"(hi) : "l"(v));
    float2 r;
    r.x = __uint_as_float(lo);
    r.y = __uint_as_float(hi);
    return r;
}

extern __shared__ unsigned char smem_raw[];

__global__ __launch_bounds__(BLOCK_THREADS)
void lbs_kernel(const float* __restrict__ points,
                const float* __restrict__ weights,
                const float* __restrict__ SE3,
                float* __restrict__ out,
                int n_verts)
{
    // SMEM: [165 x ulonglong2] packed SE3 top-3 rows (2,640 B), then [128*55] fp32 weight tile (28,160 B).
    ulonglong2* se3s = (ulonglong2*)smem_raw;
    float* wsm = (float*)(smem_raw + (size_t)N_JOINTS * 3 * sizeof(ulonglong2));

    const int t = threadIdx.x;
    const long long base = (long long)blockIdx.x * VERTS_PER_BLOCK;

    // ---- Stage SE3: pack top 3 rows of each joint as f32x2 pairs ----
    const float4* se3g = (const float4*)SE3;
    for (int i = t; i < N_JOINTS * 3; i += BLOCK_THREADS) {
        int j = i / 3;
        int r = i - 3 * j;
        float4 v = se3g[j * 4 + r];
        ulonglong2 q;
        q.x = pack2(v.x, v.y);
        q.y = pack2(v.z, v.w);
        se3s[i] = q;
    }

    // ---- Stage weight tile: coalesced float4 flat copy ----
    long long rows_ll = (long long)n_verts - base;
    int rows = rows_ll > VERTS_PER_BLOCK ? VERTS_PER_BLOCK : (int)rows_ll;
    int total = rows * N_JOINTS;
    const float* wg = weights + base * N_JOINTS;   // base multiple of 128 -> byte offset mult of 28,160 -> 16B-aligned
    const float4* wg4 = (const float4*)wg;
    float4* ws4 = (float4*)wsm;
    int nf4 = total >> 2;
    for (int i = t; i < nf4; i += BLOCK_THREADS) {
        ws4[i] = wg4[i];
    }
    for (int i = (nf4 << 2) + t; i < total; i += BLOCK_THREADS) {
        wsm[i] = wg[i];
    }
    __syncthreads();

    // ---- Compute: 1 vertex per thread ----
    const long long n0 = base + t;
    if (n0 >= n_verts) return;

    ull a0 = 0, a1 = 0, a2 = 0, a3 = 0, a4 = 0, a5 = 0;  // (A00,A01)(A02,A03)(A10,A11)(A12,A13)(A20,A21)(A22,A23)

    const float* w0p = wsm + t * N_JOINTS;               // stride 55 floats: gcd(55,32)=1 -> conflict-free

    #pragma unroll 11
    for (int j = 0; j < N_JOINTS; j++) {
        ulonglong2 q0 = se3s[3 * j + 0];  // uniform broadcast LDS.128
        ulonglong2 q1 = se3s[3 * j + 1];
        ulonglong2 q2 = se3s[3 * j + 2];
        ull wa = dup2(w0p[j]);
        a0 = fma2(wa, q0.x, a0);  a1 = fma2(wa, q0.y, a1);
        a2 = fma2(wa, q1.x, a2);  a3 = fma2(wa, q1.y, a3);
        a4 = fma2(wa, q2.x, a4);  a5 = fma2(wa, q2.y, a5);
    }

    // ---- Epilogue: out = R*p + T ----
    const float* pp = points + n0 * 3;
    float px = pp[0], py = pp[1], pz = pp[2];
    float2 r0 = unpack2(a0), r1 = unpack2(a1);
    float2 r2 = unpack2(a2), r3 = unpack2(a3);
    float2 r4 = unpack2(a4), r5 = unpack2(a5);
    float* op = out + n0 * 3;
    op[0] = fmaf(r0.x, px, fmaf(r0.y, py, fmaf(r1.x, pz, r1.y)));
    op[1] = fmaf(r2.x, px, fmaf(r2.y, py, fmaf(r3.x, pz, r3.y)));
    op[2] = fmaf(r4.x, px, fmaf(r4.y, py, fmaf(r5.x, pz, r5.y)));
}

extern "C" void kernel_launch(void* const* d_in, const int* in_sizes, int n_in,
                              void* d_out, int out_size)
{
    const float* points  = (const float*)d_in[0];  // [N, 3]
    const float* weights = (const float*)d_in[1];  // [N, 55]
    const float* SE3     = (const float*)d_in[2];  // [55, 4, 4]
    float* out = (float*)d_out;                    // [N, 3]

    const int n_verts = in_sizes[0] / 3;
    const int nblocks = (n_verts + VERTS_PER_BLOCK - 1) / VERTS_PER_BLOCK;
    const size_t smem = (size_t)N_JOINTS * 3 * sizeof(ulonglong2)
                      + (size_t)VERTS_PER_BLOCK * N_JOINTS * sizeof(float);  // 30,800 B

    cudaFuncSetAttribute(lbs_kernel, cudaFuncAttributeMaxDynamicSharedMemorySize, (int)smem);
    lbs_kernel<<<nblocks, BLOCK_THREADS, smem>>>(points, weights, SE3, out, n_verts);
}